// round 6
// baseline (speedup 1.0000x reference)
#include <cuda_runtime.h>
#include <cstdint>

#define PP 8
#define BB 256
#define NN 512
#define KK 64
#define THREADS 256
#define CHUNK_FLOATS 4096           // 16 KB chunks; tile = 32768 floats = 8 chunks

// n = N*rho^2 = 510.976512 ; g = 0.5*(log(1+rho)-log(1-rho))/rho
#define G_CONST  3.8040054350965846f
#define INV_N    0.00195703687008f

__device__ __forceinline__ void cp_async16(uint32_t smem, const void* g) {
    asm volatile("cp.async.cg.shared.global [%0], [%1], 16;\n" :: "r"(smem), "l"(g));
}
__device__ __forceinline__ void cp_commit() {
    asm volatile("cp.async.commit_group;\n" ::: "memory");
}
template <int N>
__device__ __forceinline__ void cp_wait() {
    asm volatile("cp.async.wait_group %0;\n" :: "n"(N) : "memory");
}

__device__ __forceinline__ void stage_chunk(float* dst, const float* src, int tid) {
    uint32_t s = (uint32_t)__cvta_generic_to_shared(dst);
    const float4* g = (const float4*)src;
    #pragma unroll
    for (int q = 0; q < 4; q++) {
        int i = tid + THREADS * q;          // 1024 float4 per chunk
        cp_async16(s + 16u * i, g + i);
    }
}

__global__ __launch_bounds__(THREADS, 5)
void ghu_kernel(const float* __restrict__ WL,
                const float* __restrict__ WR,
                const float* __restrict__ v_tm1,
                const float* __restrict__ v_t,
                const int*   __restrict__ ac_idx,
                const int*   __restrict__ pc_mask,
                float* __restrict__ out) {
    const int b = blockIdx.x;
    const int p = blockIdx.y;
    const int tid  = threadIdx.x;
    const int warp = tid >> 5;
    const int lane = tid & 31;

    const bool sel = (ac_idx[b] == p);
    const bool msk = (pc_mask[b * PP + p] != 0);

    float* out_vnext = out;                                    // [B,N]
    float* out_dWL   = out + (size_t)BB * NN;                  // [P,B,N,1]
    float* out_dWR   = out_dWL + (size_t)PP * BB * NN;         // [P,B,1,N]
    float* dWLrow = out_dWL + ((size_t)p * BB + b) * NN;
    float* dWRrow = out_dWR + ((size_t)p * BB + b) * NN;
    const float* vtm1_row = v_tm1 + (size_t)b * NN;
    const float* vt_row   = v_t   + (size_t)b * NN;

    // ---- dWR needs no weight data: vectorized write ----
    if (tid < NN / 4) {
        float4 vv = ((const float4*)vtm1_row)[tid];
        float4 o;
        if (msk) { o.x = vv.x * INV_N; o.y = vv.y * INV_N;
                   o.z = vv.z * INV_N; o.w = vv.w * INV_N; }
        else     { o = make_float4(0.f, 0.f, 0.f, 0.f); }
        ((float4*)dWRrow)[tid] = o;
    }

    // Unneeded tiles: zero dWL, done. No weight reads.
    if (!msk && !sel) {
        if (tid < NN / 4)
            ((float4*)dWLrow)[tid] = make_float4(0.f, 0.f, 0.f, 0.f);
        return;
    }

    __shared__ float sbuf[2][CHUNK_FLOATS];   // 32 KB double buffer
    __shared__ float sv_t[NN];
    __shared__ float sv_tm1[NN];
    __shared__ float sWRx[KK];
    __shared__ float sWx[KK];
    __shared__ float sAcc1[NN];
    __shared__ float sAcc2[NN];

    if (tid < NN / 4) {
        ((float4*)sv_t)[tid]   = ((const float4*)vt_row)[tid];
        ((float4*)sv_tm1)[tid] = ((const float4*)vtm1_row)[tid];
    }

    const size_t tileOff = ((size_t)p * BB + b) * (size_t)(NN * KK);
    const float* WRt = WR + tileOff;   // [K, N], contiguous 32768 floats
    const float* WLt = WL + tileOff;   // [N, K], contiguous 32768 floats

    // Prefetch chunk 0 (WR rows 0..7)
    stage_chunk(sbuf[0], WRt, tid);
    cp_commit();

    // 16 chunks: 0..7 = WR (phase A), 8..15 = WL (phase B).
    #pragma unroll 1
    for (int c = 0; c < 16; c++) {
        if (c < 15) {
            const float* src = (c + 1 < 8)
                ? (WRt + (size_t)CHUNK_FLOATS * (c + 1))
                : (WLt + (size_t)CHUNK_FLOATS * (c + 1 - 8));
            stage_chunk(sbuf[(c + 1) & 1], src, tid);
            cp_commit();
            cp_wait<1>();
        } else {
            cp_wait<0>();
        }
        __syncthreads();   // chunk c visible to all; also covers sv_t/sv_tm1 on c=0

        const float* buf = sbuf[c & 1];

        if (c < 8) {
            // ---- Phase A: warp w handles k-row (8c + w) of WR ----
            const float* row = buf + warp * NN;
            float a1 = 0.f, a2 = 0.f;
            #pragma unroll
            for (int j = 0; j < 4; j++) {
                const int idx  = lane + 32 * j;
                const int base = 4 * idx;
                float4 w = ((const float4*)row)[idx];
                a1 = fmaf(w.x, sv_tm1[base+0], fmaf(w.y, sv_tm1[base+1],
                     fmaf(w.z, sv_tm1[base+2], fmaf(w.w, sv_tm1[base+3], a1))));
                a2 = fmaf(w.x, sv_t[base+0], fmaf(w.y, sv_t[base+1],
                     fmaf(w.z, sv_t[base+2], fmaf(w.w, sv_t[base+3], a2))));
            }
            #pragma unroll
            for (int o = 16; o > 0; o >>= 1) {
                a1 += __shfl_xor_sync(0xFFFFFFFFu, a1, o);
                a2 += __shfl_xor_sync(0xFFFFFFFFu, a2, o);
            }
            if (lane == 0) {
                sWRx[8 * c + warp] = a1;
                sWx [8 * c + warp] = a2;
            }
        } else {
            // ---- Phase B: 16-lane group g handles 4 n-rows of this WL chunk ----
            const int cb = c - 8;
            const int g  = tid >> 4;
            const int hl = tid & 15;
            float4 s1 = ((const float4*)sWRx)[hl];
            float4 s2 = ((const float4*)sWx)[hl];
            float a1r[4], a2r[4];
            #pragma unroll
            for (int r = 0; r < 4; r++) {
                float4 w = ((const float4*)(buf + (4 * g + r) * KK))[hl];
                a1r[r] = w.x*s1.x + w.y*s1.y + w.z*s1.z + w.w*s1.w;
                a2r[r] = w.x*s2.x + w.y*s2.y + w.z*s2.z + w.w*s2.w;
            }
            #pragma unroll
            for (int o = 8; o > 0; o >>= 1) {
                #pragma unroll
                for (int r = 0; r < 4; r++) {
                    a1r[r] += __shfl_xor_sync(0xFFFFFFFFu, a1r[r], o);
                    a2r[r] += __shfl_xor_sync(0xFFFFFFFFu, a2r[r], o);
                }
            }
            if (hl == 0) {
                const int n0 = 64 * cb + 4 * g;
                #pragma unroll
                for (int r = 0; r < 4; r++) {
                    sAcc1[n0 + r] = a1r[r];
                    sAcc2[n0 + r] = a2r[r];
                }
            }
        }
        __syncthreads();   // buffer may be overwritten next iteration
    }

    // ---- Final vectorized writes: threads 0-127 -> dWL, 128-255 -> v_next ----
    if (tid < 128) {
        float4 o;
        if (msk) {
            float4 a = ((const float4*)sAcc1)[tid];
            float4 t = ((const float4*)sv_t)[tid];
            o.x = G_CONST * t.x - a.x;
            o.y = G_CONST * t.y - a.y;
            o.z = G_CONST * t.z - a.z;
            o.w = G_CONST * t.w - a.w;
        } else {
            o = make_float4(0.f, 0.f, 0.f, 0.f);
        }
        ((float4*)dWLrow)[tid] = o;
    } else if (sel) {
        const int i = tid - 128;
        float4 a = ((const float4*)sAcc2)[i];
        float4 o;
        o.x = tanhf(a.x); o.y = tanhf(a.y);
        o.z = tanhf(a.z); o.w = tanhf(a.w);
        ((float4*)(out_vnext + (size_t)b * NN))[i] = o;
    }
}

extern "C" void kernel_launch(void* const* d_in, const int* in_sizes, int n_in,
                              void* d_out, int out_size) {
    const float* WL    = (const float*)d_in[0];
    const float* WR    = (const float*)d_in[1];
    const float* v_tm1 = (const float*)d_in[2];
    const float* v_t   = (const float*)d_in[3];
    const int*   ac    = (const int*)d_in[4];
    const int*   pcm   = (const int*)d_in[5];
    float* out = (float*)d_out;

    dim3 grid(BB, PP);
    ghu_kernel<<<grid, THREADS>>>(WL, WR, v_tm1, v_t, ac, pcm, out);
}